// round 10
// baseline (speedup 1.0000x reference)
#include <cuda_runtime.h>
#include <cstdint>

// Problem constants: B=128, C=3, H=W=256, PROB=0.9, BRI=CON=SAT=0.2, CUT=0.25 -> CH=CW=64.
#define PROB_ 0.9f
static constexpr int B_     = 128;
static constexpr int H_     = 256;
static constexpr int W_     = 256;
static constexpr int CH_    = 64;
static constexpr int CW_    = 64;
static constexpr int PLANE  = H_ * W_;     // 65536 floats
static constexpr int PLANE4 = PLANE / 4;   // 16384 float4
static constexpr int NT     = 1024;        // threads per block
static constexpr int A4     = 4096;        // float4 per channel in region A (rows 0-63)
static constexpr int ITA    = A4 / NT;     // 4  iters over region A per channel
static constexpr int ITB    = (PLANE4 - A4) / NT;  // 12 iters over region B per channel
static constexpr int SMEM_BYTES = 3 * A4 * 16;     // 192KB region-A cache

// ---------------------------------------------------------------------------
// One block = one batch, single wave (128 CTAs), no clusters.
//
// Phase 1 (overlapped): issue cp.async of region A (rows 0-63, 3 channels,
// 192KB) into SMEM, then sum region B (rows 64-255) via __ldg while A streams;
// finally wait per-channel groups and sum A from SMEM. Loads overlap FADDs.
//
// Phase 2: region B newest-first via __ldcs (last-use; these lines are the
// L2-hot tail of phase 1), then region A from SMEM (no L2 traffic at all --
// A's lines are the oldest and most likely evicted, so caching them in SMEM
// removes phase-2's DRAM re-read). Stores via __stcs (output never re-read).
//
// Algebra: out_ch = A*x0_ch + D*g0 + E_ch with
//   A = s*b*c ; D = (1-s)*b*c ; g0 = mean_ch(x0 pixel)
//   E_ch = (1-c)*(s*M_ch + (1-s)*Mbar),  M_ch = b*mean(raw plane ch)
// flip reverses W only (row/region membership unchanged); flip preserves means.
// ---------------------------------------------------------------------------
__global__ __launch_bounds__(NT) void batch_kernel(
    const float* __restrict__ img,
    const float* __restrict__ apply_u,
    const float* __restrict__ flip_u,
    const float* __restrict__ bri_u,
    const float* __restrict__ con_u,
    const float* __restrict__ sat_u,
    const int*   __restrict__ top_idx,
    const int*   __restrict__ left_idx,
    float* __restrict__ out)
{
    extern __shared__ float4 smA4[];   // [3][A4] region-A tiles

    const int b   = blockIdx.x;
    const int tid = threadIdx.x;

    const float4* p0 = reinterpret_cast<const float4*>(img + (size_t)b * 3 * PLANE);
    const float4* p1 = p0 + PLANE4;
    const float4* p2 = p0 + 2 * PLANE4;
    float4* o0 = reinterpret_cast<float4*>(out + (size_t)b * 3 * PLANE);
    float4* o1 = o0 + PLANE4;
    float4* o2 = o0 + 2 * PLANE4;

    const bool apply = (__ldg(apply_u + b) < PROB_);

    if (!apply) {
        // Single-pass streaming copy (uniform per block).
#pragma unroll
        for (int i = 0; i < ITA + ITB; i++) {
            const int idx = tid + i * NT;
            __stcs(o0 + idx, __ldcs(p0 + idx));
            __stcs(o1 + idx, __ldcs(p1 + idx));
            __stcs(o2 + idx, __ldcs(p2 + idx));
        }
        return;
    }

    // ---------------- Phase 1a: launch region-A cp.async (3 groups) --------
    const uint32_t sbase = (uint32_t)__cvta_generic_to_shared(smA4);
#pragma unroll
    for (int ch = 0; ch < 3; ch++) {
        const float4* src = (ch == 0) ? p0 : (ch == 1) ? p1 : p2;
#pragma unroll
        for (int i = 0; i < ITA; i++) {
            const int j = tid + i * NT;
            const uint32_t dst = sbase + (uint32_t)(ch * A4 + j) * 16u;
            asm volatile("cp.async.cg.shared.global [%0], [%1], 16;\n"
                         :: "r"(dst), "l"(src + j));
        }
        asm volatile("cp.async.commit_group;\n");
    }

    // ---------------- Phase 1b: sum region B via __ldg (overlaps cp.async) --
    float s0 = 0.0f, s1 = 0.0f, s2 = 0.0f;
#pragma unroll
    for (int i = 0; i < ITB; i++) {
        const int j = A4 + tid + i * NT;
        float4 a = __ldg(p0 + j);
        float4 d = __ldg(p1 + j);
        float4 e = __ldg(p2 + j);
        s0 += (a.x + a.y) + (a.z + a.w);
        s1 += (d.x + d.y) + (d.z + d.w);
        s2 += (e.x + e.y) + (e.z + e.w);
    }

    // ---------------- Phase 1c: sum region A from SMEM as groups land ------
    {
        asm volatile("cp.async.wait_group 2;\n" ::: "memory");
#pragma unroll
        for (int i = 0; i < ITA; i++) {
            float4 v = smA4[tid + i * NT];
            s0 += (v.x + v.y) + (v.z + v.w);
        }
        asm volatile("cp.async.wait_group 1;\n" ::: "memory");
#pragma unroll
        for (int i = 0; i < ITA; i++) {
            float4 v = smA4[A4 + tid + i * NT];
            s1 += (v.x + v.y) + (v.z + v.w);
        }
        asm volatile("cp.async.wait_group 0;\n" ::: "memory");
#pragma unroll
        for (int i = 0; i < ITA; i++) {
            float4 v = smA4[2 * A4 + tid + i * NT];
            s2 += (v.x + v.y) + (v.z + v.w);
        }
    }

#pragma unroll
    for (int o = 16; o > 0; o >>= 1) {
        s0 += __shfl_xor_sync(0xFFFFFFFFu, s0, o);
        s1 += __shfl_xor_sync(0xFFFFFFFFu, s1, o);
        s2 += __shfl_xor_sync(0xFFFFFFFFu, s2, o);
    }

    __shared__ float smW[3][32];
    __shared__ float smMean[3];
    const int wid = tid >> 5;
    if ((tid & 31) == 0) { smW[0][wid] = s0; smW[1][wid] = s1; smW[2][wid] = s2; }
    __syncthreads();   // also publishes region-A SMEM tiles for flipped reads
    if (tid < 32) {
        float a = smW[0][tid], d = smW[1][tid], e = smW[2][tid];
#pragma unroll
        for (int o = 16; o > 0; o >>= 1) {
            a += __shfl_xor_sync(0xFFFFFFFFu, a, o);
            d += __shfl_xor_sync(0xFFFFFFFFu, d, o);
            e += __shfl_xor_sync(0xFFFFFFFFu, e, o);
        }
        if (tid == 0) {
            const float inv = 1.0f / (float)PLANE;
            smMean[0] = a * inv; smMean[1] = d * inv; smMean[2] = e * inv;
        }
    }
    __syncthreads();

    // ---------------- Per-batch constants -----------------------------------
    const float bv = 0.8f + 0.4f * __ldg(bri_u + b);
    const float cv = 0.8f + 0.4f * __ldg(con_u + b);
    const float sv = 0.8f + 0.4f * __ldg(sat_u + b);

    const float M0 = smMean[0] * bv;
    const float M1 = smMean[1] * bv;
    const float M2 = smMean[2] * bv;
    const float Mbar = (M0 + M1 + M2) * (1.0f / 3.0f);

    const float A  = sv * bv * cv;
    const float D  = (1.0f - sv) * bv * cv;
    const float k  = 1.0f - cv;
    const float os = 1.0f - sv;
    const float E0 = k * (sv * M0 + os * Mbar);
    const float E1 = k * (sv * M1 + os * Mbar);
    const float E2 = k * (sv * M2 + os * Mbar);

    const bool flip = (__ldg(flip_u + b) < 0.5f);
    const int  t_   = __ldg(top_idx + b);
    const int  l_   = __ldg(left_idx + b);

    // Transform macro body (shared by both regions).
#define XFORM_AND_STORE(rv, gv, cv4, hrow, wgrp, oidx)                          \
    do {                                                                        \
        if (flip) {                                                             \
            float t;                                                            \
            t = rv.x; rv.x = rv.w; rv.w = t;  t = rv.y; rv.y = rv.z; rv.z = t;  \
            t = gv.x; gv.x = gv.w; gv.w = t;  t = gv.y; gv.y = gv.z; gv.z = t;  \
            t = cv4.x; cv4.x = cv4.w; cv4.w = t; t = cv4.y; cv4.y = cv4.z; cv4.z = t; \
        }                                                                       \
        const bool row_in = (hrow >= t_) && (hrow < t_ + CH_);                  \
        const int  w0 = (wgrp) << 2;                                            \
        float4 oR, oG, oB; float gray; bool cut; int col;                       \
        col = w0 + 0; cut = row_in && (col >= l_) && (col < l_ + CW_);          \
        gray = (rv.x + gv.x + cv4.x) * (1.0f / 3.0f);                           \
        oR.x = cut ? 0.0f : fmaf(A, rv.x, fmaf(D, gray, E0));                   \
        oG.x = cut ? 0.0f : fmaf(A, gv.x, fmaf(D, gray, E1));                   \
        oB.x = cut ? 0.0f : fmaf(A, cv4.x, fmaf(D, gray, E2));                  \
        col = w0 + 1; cut = row_in && (col >= l_) && (col < l_ + CW_);          \
        gray = (rv.y + gv.y + cv4.y) * (1.0f / 3.0f);                           \
        oR.y = cut ? 0.0f : fmaf(A, rv.y, fmaf(D, gray, E0));                   \
        oG.y = cut ? 0.0f : fmaf(A, gv.y, fmaf(D, gray, E1));                   \
        oB.y = cut ? 0.0f : fmaf(A, cv4.y, fmaf(D, gray, E2));                  \
        col = w0 + 2; cut = row_in && (col >= l_) && (col < l_ + CW_);          \
        gray = (rv.z + gv.z + cv4.z) * (1.0f / 3.0f);                           \
        oR.z = cut ? 0.0f : fmaf(A, rv.z, fmaf(D, gray, E0));                   \
        oG.z = cut ? 0.0f : fmaf(A, gv.z, fmaf(D, gray, E1));                   \
        oB.z = cut ? 0.0f : fmaf(A, cv4.z, fmaf(D, gray, E2));                  \
        col = w0 + 3; cut = row_in && (col >= l_) && (col < l_ + CW_);          \
        gray = (rv.w + gv.w + cv4.w) * (1.0f / 3.0f);                           \
        oR.w = cut ? 0.0f : fmaf(A, rv.w, fmaf(D, gray, E0));                   \
        oG.w = cut ? 0.0f : fmaf(A, gv.w, fmaf(D, gray, E1));                   \
        oB.w = cut ? 0.0f : fmaf(A, cv4.w, fmaf(D, gray, E2));                  \
        __stcs(o0 + (oidx), oR);                                                \
        __stcs(o1 + (oidx), oG);                                                \
        __stcs(o2 + (oidx), oB);                                                \
    } while (0)

    // ---------------- Phase 2a: region B, newest-first, last-use loads -----
#pragma unroll
    for (int i = ITB - 1; i >= 0; i--) {
        const int idx = A4 + tid + i * NT;   // output float4 index in plane
        const int h   = idx >> 6;            // row 64..255
        const int wg  = idx & 63;
        const int sw  = flip ? (63 - wg) : wg;
        const int sidx = (h << 6) + sw;

        float4 r = __ldcs(p0 + sidx);
        float4 g = __ldcs(p1 + sidx);
        float4 c = __ldcs(p2 + sidx);
        XFORM_AND_STORE(r, g, c, h, wg, idx);
    }

    // ---------------- Phase 2b: region A from SMEM (zero L2 traffic) -------
#pragma unroll
    for (int i = 0; i < ITA; i++) {
        const int idx = tid + i * NT;        // float4 index, rows 0..63
        const int h   = idx >> 6;
        const int wg  = idx & 63;
        const int sj  = (h << 6) + (flip ? (63 - wg) : wg);

        float4 r = smA4[sj];
        float4 g = smA4[A4 + sj];
        float4 c = smA4[2 * A4 + sj];
        XFORM_AND_STORE(r, g, c, h, wg, idx);
    }
#undef XFORM_AND_STORE
}

extern "C" void kernel_launch(void* const* d_in, const int* in_sizes, int n_in,
                              void* d_out, int out_size) {
    const float* images       = (const float*)d_in[0];
    const float* apply_u      = (const float*)d_in[1];
    const float* flip_u       = (const float*)d_in[2];
    const float* brightness_u = (const float*)d_in[3];
    const float* contrast_u   = (const float*)d_in[4];
    const float* saturation_u = (const float*)d_in[5];
    const int*   top_idx      = (const int*)d_in[6];
    const int*   left_idx     = (const int*)d_in[7];
    float* out = (float*)d_out;

    cudaFuncSetAttribute(batch_kernel,
                         cudaFuncAttributeMaxDynamicSharedMemorySize,
                         SMEM_BYTES);

    batch_kernel<<<B_, NT, SMEM_BYTES>>>(images, apply_u, flip_u, brightness_u,
                                         contrast_u, saturation_u, top_idx,
                                         left_idx, out);
}